// round 12
// baseline (speedup 1.0000x reference)
#include <cuda_runtime.h>
#include <cuda_bf16.h>

// Problem constants (fixed by the reference): B=256, T=2048, L=4, H=64, P=1.
#define BSZ   256
#define TLEN  2048
#define NLAY  4
#define HID   64
#define CHUNK 32          // timesteps per BSP iteration (= warp width)
#define NCH   (TLEN/CHUNK)

#define L2E 1.4426950408889634f   // log2(e)

__device__ __forceinline__ float ex2(float x) {
    float r; asm("ex2.approx.ftz.f32 %0, %1;" : "=f"(r) : "f"(x)); return r;
}
__device__ __forceinline__ float rcpa(float x) {
    float r; asm("rcp.approx.ftz.f32 %0, %1;" : "=f"(r) : "f"(x)); return r;
}
__device__ __forceinline__ float wsum(float v) {
    v += __shfl_xor_sync(0xffffffffu, v, 16);
    v += __shfl_xor_sync(0xffffffffu, v, 8);
    v += __shfl_xor_sync(0xffffffffu, v, 4);
    v += __shfl_xor_sync(0xffffffffu, v, 2);
    v += __shfl_xor_sync(0xffffffffu, v, 1);
    return v;
}

// Per-layer, per-lane register weights. Pre-scaled so the gate FMA directly
// yields the EX2 argument: sigm gates a=-L2E*g -> sigm=1/(1+2^a);
// tanh gate a=-2*L2E*g -> tanh=(1-2^a)/(1+2^a).
struct Lw { float wi[8], wh[8], bs[8], wr0, wr1; };

__device__ __forceinline__ void load_layer(
    Lw& L, int l, int ln,
    const float* __restrict__ Wih, const float* __restrict__ Whh,
    const float* __restrict__ bih, const float* __restrict__ bhh,
    const float* __restrict__ Whr)
{
    const float* wih_l = Wih + l * 4 * HID;
    const float* whh_l = Whh + l * 4 * HID;
    const float* bih_l = bih + l * 4 * HID;
    const float* bhh_l = bhh + l * 4 * HID;
#pragma unroll
    for (int j = 0; j < 8; ++j) {
        int gate = j >> 1;                      // 0:i 1:f 2:g 3:o
        int idx  = gate * 64 + ln + (j & 1) * 32;
        float s  = (gate == 2) ? (-2.0f * L2E) : (-L2E);
        L.wi[j] = s * wih_l[idx];
        L.wh[j] = s * whh_l[idx];
        L.bs[j] = s * (bih_l[idx] + bhh_l[idx]);
    }
    L.wr0 = Whr[l * HID + ln];
    L.wr1 = Whr[l * HID + ln + 32];
}

// One LSTM recurrence step for 2 cells/lane. Lane ln owns cells {ln, ln+32}.
// Two 4-wide Montgomery trees (one rcp each) for the 8 gate denominators;
// per-c rcp for tanh(c). MUFU/step: 10 ex2 + 4 rcp. Returns new h (allreduced).
__device__ __forceinline__ float lstm_step(const Lw& L, float x,
                                           float& h, float& c0, float& c1)
{
    float xb[8], e[8], d[8];
#pragma unroll
    for (int j = 0; j < 8; ++j) xb[j] = fmaf(x, L.wi[j], L.bs[j]);  // off-chain
#pragma unroll
    for (int j = 0; j < 8; ++j) {
        float a = fminf(fmaf(h, L.wh[j], xb[j]), 30.0f);  // 4-prod < 2^120, inf-safe
        e[j] = ex2(a);
        d[j] = 1.0f + e[j];
    }
    // tree 1: i, f
    float p01 = d[0] * d[1], p23 = d[2] * d[3];
    float rIF = rcpa(p01 * p23);
    float r01 = rIF * p23,   r23 = rIF * p01;
    float i0 = r01 * d[1],   i1 = r01 * d[0];
    float f0 = r23 * d[3],   f1 = r23 * d[2];
    // tree 2: g, o (runs in parallel with tree 1)
    float p45 = d[4] * d[5], p67 = d[6] * d[7];
    float rGO = rcpa(p45 * p67);
    float r45 = rGO * p67,   r67 = rGO * p45;
    float g0 = r45 * d[5],   g1 = r45 * d[4];
    float o0 = r67 * d[7],   o1 = r67 * d[6];

    float tg0 = (1.0f - e[4]) * g0;   // tanh(g)
    float tg1 = (1.0f - e[5]) * g1;

    c0 = fmaf(f0, c0, i0 * tg0);
    c1 = fmaf(f1, c1, i1 * tg1);

    float ow0 = o0 * L.wr0, ow1 = o1 * L.wr1;          // off-chain while tanh(c) runs

    float ac0 = fminf(c0 * (-2.0f * L2E), 30.0f);
    float ac1 = fminf(c1 * (-2.0f * L2E), 30.0f);
    float ec0 = ex2(ac0), ec1 = ex2(ac1);
    float tc0 = (1.0f - ec0) * rcpa(1.0f + ec0);       // tanh(c), independent rcps
    float tc1 = (1.0f - ec1) * rcpa(1.0f + ec1);

    float part = fmaf(ow0, tc0, ow1 * tc1);
    h = wsum(part);                                    // 64-wide allreduce (5 bfly)
    return h;
}

// One block per batch element, 2 warps. Warp w runs layers {2w, 2w+1} as two
// interleaved wavefront chains (layer l processes chunk it-l at iteration it):
// chain B's issue fills chain A's latency bubbles; max 1 warp per SMSP chip-wide.
// Layer0<-gmem prefetch; 0->1 and 2->3 handoffs are intra-warp registers;
// 1->2 via double-buffered smem ring + one __syncthreads per iteration.
__global__ __launch_bounds__(64) void lstm_dual_kernel(
    const float* __restrict__ y,     // [B, T, 1]
    const float* __restrict__ Wih,   // [L, 256, 1]
    const float* __restrict__ Whh,   // [L, 256, 1]
    const float* __restrict__ bih,   // [L, 256]
    const float* __restrict__ bhh,   // [L, 256]
    const float* __restrict__ Whr,   // [L, 1, 64]
    const int*   __restrict__ mslp,
    float*       __restrict__ out)   // [B, T-msl, 1]
{
    __shared__ float ring_s[2][CHUNK];

    const int b  = blockIdx.x;
    const int w  = threadIdx.x >> 5;   // warp id: 0 -> layers 0,1; 1 -> layers 2,3
    const int ln = threadIdx.x & 31;
    const int la = 2 * w, lb = la + 1;

    Lw A, B;
    load_layer(A, la, ln, Wih, Whh, bih, bhh, Whr);
    load_layer(B, lb, ln, Wih, Whh, bih, bhh, Whr);

    const int   msl = *mslp;
    const int   To  = TLEN - msl;
    const float* yb = y + b * TLEN;

    float hA = 0.f, cA0 = 0.f, cA1 = 0.f;
    float hB = 0.f, cB0 = 0.f, cB1 = 0.f;
    float keepA = 0.f;                       // chain A's chunk from previous iteration
    float xpre  = (w == 0) ? yb[ln] : 0.f;   // prefetch chunk 0 for layer 0

    const int NIT = NCH + NLAY - 1;          // 67 wavefront iterations
    for (int it = 0; it < NIT; ++it) {
        // ---- inputs ----
        float xB = keepA;                    // layer lb chunk it-lb == A's prev output
        float xA;
        if (w == 0) {
            xA   = xpre;
            xpre = (it + 1 < NCH) ? yb[(it + 1) * CHUNK + ln] : 0.f;  // off-chain
        } else {
            xA = ring_s[(it + 1) & 1][ln];   // layer1 chunk it-2, written at it-1
        }

        // ---- state reset at each chain's first real chunk (kills garbage warm-up) ----
        if (it == la) { hA = 0.f; cA0 = 0.f; cA1 = 0.f; }
        if (it == lb) { hB = 0.f; cB0 = 0.f; cB1 = 0.f; }

        // ---- 32 interleaved step-pairs ----
        float keepAn = 0.f, keepBn = 0.f;
#pragma unroll 4
        for (int tt = 0; tt < CHUNK; ++tt) {
            float xa = __shfl_sync(0xffffffffu, xA, tt);
            float xb = __shfl_sync(0xffffffffu, xB, tt);
            lstm_step(A, xa, hA, cA0, cA1);   // independent chains — scheduler
            lstm_step(B, xb, hB, cB0, cB1);   // interleaves them
            keepAn = (tt == ln) ? hA : keepAn;
            keepBn = (tt == ln) ? hB : keepBn;
        }
        keepA = keepAn;

        // ---- publish ----
        if (w == 0) {
            ring_s[it & 1][ln] = keepBn;                  // layer1 chunk it-1 -> layer2
        } else if (it >= 3) {
            int t = (it - 3) * CHUNK + ln;                // layer3 chunk it-3
            if (t >= msl) out[b * To + (t - msl)] = keepBn;
        }

        __syncthreads();   // RAW+WAR for the double-buffered ring (2 warps, cheap)
    }
}

extern "C" void kernel_launch(void* const* d_in, const int* in_sizes, int n_in,
                              void* d_out, int out_size) {
    const float* y    = (const float*)d_in[0];
    const float* Wih  = (const float*)d_in[1];
    const float* Whh  = (const float*)d_in[2];
    const float* bih  = (const float*)d_in[3];
    const float* bhh  = (const float*)d_in[4];
    const float* Whr  = (const float*)d_in[5];
    const int*   msl  = (const int*)  d_in[6];
    float* out = (float*)d_out;
    (void)in_sizes; (void)n_in; (void)out_size;

    lstm_dual_kernel<<<BSZ, 64>>>(y, Wih, Whh, bih, bhh, Whr, msl, out);
}